// round 7
// baseline (speedup 1.0000x reference)
#include <cuda_runtime.h>
#include <math.h>

#define N_TOK 65536
#define DIM 64
#define KCODE 512
#define IN_DIM 256

typedef unsigned long long ull;

#define CVT_TF32(u, f) asm("cvt.rna.tf32.f32 %0, %1;" : "=r"(u) : "f"(f))

#define MMA_TF32(c0, c1, c2, c3, a0, a1, a2, a3, b0, b1)                     \
    asm volatile(                                                            \
        "mma.sync.aligned.m16n8k8.row.col.f32.tf32.tf32.f32 "                \
        "{%0,%1,%2,%3}, {%4,%5,%6,%7}, {%8,%9}, {%0,%1,%2,%3};"              \
        : "+f"(c0), "+f"(c1), "+f"(c2), "+f"(c3)                             \
        : "r"(a0), "r"(a1), "r"(a2), "r"(a3), "r"(b0), "r"(b1))

// ---------------- device scratch (16B-aligned) ----------------
__device__ __align__(16) float g_zT[DIM * N_TOK];        // 2*z transposed [d][n]
__device__ __align__(16) float g_A[N_TOK];               // bit-exact ||z||^2
__device__ __align__(16) float g_B[KCODE];               // bit-exact ||e||^2
__device__ __align__(16) float g_eT[DIM * KCODE];        // codebook transposed
__device__ __align__(16) float g_table[KCODE * IN_DIM];  // cb @ dec_w
__device__ __align__(16) int g_idx[N_TOK];
__device__ __align__(16) unsigned int g_counts[KCODE];
__device__ __align__(16) float g_loss_part[256];

// ---------------- setup: transpose cb, zero counts, B[k] bit-exact --------
__global__ void k_setup(const float* __restrict__ cb) {
    int b = blockIdx.x, t = threadIdx.x;
    if (b < 64) {                       // transpose: eT[d][k] = cb[k][d]
        g_eT[b * KCODE + t]       = cb[(size_t)t * DIM + b];
        g_eT[b * KCODE + 256 + t] = cb[(size_t)(256 + t) * DIM + b];
    } else {                            // b == 64: counts + norms
        int k0 = t, k1 = t + 256;
        g_counts[k0] = 0u; g_counts[k1] = 0u;
        const float* e0 = cb + (size_t)k0 * DIM;
        const float* e1 = cb + (size_t)k1 * DIM;
        float s0 = 0.f, s1 = 0.f;
        for (int d = 0; d < DIM; d++) {
            s0 = __fadd_rn(s0, __fmul_rn(e0[d], e0[d]));
            s1 = __fadd_rn(s1, __fmul_rn(e1[d], e1[d]));
        }
        g_B[k0] = s0; g_B[k1] = s1;
    }
}

// ---------------- table[k][i] = sum_d cb[k][d] * dec_w[d][i] ----------------
__global__ void k_table(const float* __restrict__ cb, const float* __restrict__ dw) {
    __shared__ float e[DIM];
    int k = blockIdx.x, tid = threadIdx.x;
    if (tid < DIM) e[tid] = cb[(size_t)k * DIM + tid];
    __syncthreads();
    float acc = 0.f;
    #pragma unroll 8
    for (int d = 0; d < DIM; d++)
        acc = fmaf(e[d], dw[d * IN_DIM + tid], acc);
    g_table[(size_t)k * IN_DIM + tid] = acc;
}

// ---------------- encoder: z = x @ enc_w (bit-exact chains) ---------------
// (R5 version: plain FFMA, 2 CTA/SM)
#define XCH 64
#define XPC 68
__global__ void __launch_bounds__(256, 2)
k_enc(const float* __restrict__ x, const float* __restrict__ w) {
    extern __shared__ float s[];
    float* ws = s;                   // [256][64] = 64KB
    float* xs = s + IN_DIM * DIM;    // [128][XPC]
    int tid = threadIdx.x;
    size_t rowbase = (size_t)blockIdx.x * 128;

    {   // w: linear float4 copy (once)
        const float4* wg = (const float4*)w;
        float4* w4 = (float4*)ws;
        #pragma unroll 4
        for (int i = tid; i < IN_DIM * DIM / 4; i += 256) w4[i] = wg[i];
    }

    int rg = tid >> 3, cg = tid & 7;
    float acc[4][8];
    #pragma unroll
    for (int a = 0; a < 4; a++)
        #pragma unroll
        for (int b = 0; b < 8; b++) acc[a][b] = 0.f;

    const float4* xg = (const float4*)(x + rowbase * IN_DIM);

    for (int c = 0; c < 4; c++) {
        __syncthreads();
        #pragma unroll
        for (int it = 0; it < 8; it++) {
            int idx = it * 256 + tid;
            int r = idx >> 4, q = idx & 15;
            *(float4*)(xs + r * XPC + 4 * q) = xg[(size_t)r * 64 + 16 * c + q];
        }
        __syncthreads();

        const float* xr0 = xs + (4 * rg + 0) * XPC;
        const float* xr1 = xs + (4 * rg + 1) * XPC;
        const float* xr2 = xs + (4 * rg + 2) * XPC;
        const float* xr3 = xs + (4 * rg + 3) * XPC;

        #pragma unroll
        for (int i4 = 0; i4 < XCH / 4; i4++) {
            float4 xv0 = *(const float4*)(xr0 + 4 * i4);
            float4 xv1 = *(const float4*)(xr1 + 4 * i4);
            float4 xv2 = *(const float4*)(xr2 + 4 * i4);
            float4 xv3 = *(const float4*)(xr3 + 4 * i4);
            #pragma unroll
            for (int j = 0; j < 4; j++) {
                int i = XCH * c + 4 * i4 + j;
                float4 wa = *(const float4*)(ws + i * DIM + 4 * cg);
                float4 wb = *(const float4*)(ws + i * DIM + 32 + 4 * cg);
                float wv[8] = {wa.x, wa.y, wa.z, wa.w, wb.x, wb.y, wb.z, wb.w};
                float x0 = ((const float*)&xv0)[j];
                float x1 = ((const float*)&xv1)[j];
                float x2 = ((const float*)&xv2)[j];
                float x3 = ((const float*)&xv3)[j];
                #pragma unroll
                for (int b = 0; b < 8; b++) {
                    acc[0][b] = fmaf(x0, wv[b], acc[0][b]);
                    acc[1][b] = fmaf(x1, wv[b], acc[1][b]);
                    acc[2][b] = fmaf(x2, wv[b], acc[2][b]);
                    acc[3][b] = fmaf(x3, wv[b], acc[3][b]);
                }
            }
        }
    }

    // store 2*z transposed (exact doubling)
    #pragma unroll
    for (int b = 0; b < 8; b++) {
        int col = (b < 4) ? (4 * cg + b) : (32 + 4 * cg + (b - 4));
        float4 v;
        v.x = 2.0f * acc[0][b]; v.y = 2.0f * acc[1][b];
        v.z = 2.0f * acc[2][b]; v.w = 2.0f * acc[3][b];
        *(float4*)(g_zT + (size_t)col * N_TOK + rowbase + 4 * rg) = v;
    }

    // A[n]: bit-exact sequential sum of z_d^2
    __syncthreads();
    float* zs = xs;
    #pragma unroll
    for (int a = 0; a < 4; a++)
        #pragma unroll
        for (int b = 0; b < 8; b++) {
            int col = (b < 4) ? (4 * cg + b) : (32 + 4 * cg + (b - 4));
            zs[(4 * rg + a) * 65 + col] = acc[a][b];
        }
    __syncthreads();
    if (tid < 128) {
        const float* zr = zs + tid * 65;
        float sA = 0.f;
        for (int d = 0; d < DIM; d++)
            sA = __fadd_rn(sA, __fmul_rn(zr[d], zr[d]));
        g_A[rowbase + tid] = sA;
    }
}

// ---------------- VQ: tf32 mma filter + exact fp32 recheck ----------------
// 512 thr / 16 warps, 256 tokens/block. Warp w: tokens 16w..16w+15.
// Pass 1: approx dist via mma.m16n8k8.tf32 over all 512 codes; per-token
//         approx min + 64-bit mask of n-tiles that may contain candidates.
// Pass 2: flagged tiles only; candidates get the bit-exact fp32 chain.
#define EP 516                       // eTs pitch
#define TP 260                       // zsT pitch
#define EPSF 2e-3f
__global__ void __launch_bounds__(512, 1) k_vq() {
    extern __shared__ float s[];
    float* eTs = s;                      // [64][EP]
    float* zsT = s + DIM * EP;           // [64][TP], holds 2*z
    float* Bs  = zsT + DIM * TP;         // [512]
    float* As  = Bs + KCODE;             // [256]
    float* lred = As + 256;              // [16]
    int tid = threadIdx.x;
    size_t base = (size_t)blockIdx.x * 256;

    {   // eTs: 64 x 512 -> pitched
        const float4* eg = (const float4*)g_eT;
        #pragma unroll
        for (int it = 0; it < 16; it++) {
            int idx = it * 512 + tid;
            int row = idx >> 7, q = idx & 127;
            *(float4*)(eTs + row * EP + 4 * q) = eg[idx];
        }
        // zsT: 64 x 256 tokens
        #pragma unroll
        for (int it = 0; it < 8; it++) {
            int idx = it * 512 + tid;
            int row = idx >> 6, q = idx & 63;
            *(float4*)(zsT + row * TP + 4 * q) =
                *(const float4*)(g_zT + (size_t)row * N_TOK + base + 4 * q);
        }
        if (tid < KCODE) Bs[tid] = g_B[tid];
        if (tid < 256) As[tid] = g_A[base + tid];
    }
    __syncthreads();

    int w = tid >> 5, lane = tid & 31;
    int g = lane >> 2, tig = lane & 3;
    int tok0 = 16 * w;
    int t0 = tok0 + g, t1 = tok0 + g + 8;

    // precompute tf32 A-fragments (2z) for 8 k-steps
    unsigned afr[8][4];
    #pragma unroll
    for (int ks = 0; ks < 8; ks++) {
        int k0 = 8 * ks;
        CVT_TF32(afr[ks][0], zsT[(k0 + tig) * TP + t0]);
        CVT_TF32(afr[ks][1], zsT[(k0 + tig) * TP + t1]);
        CVT_TF32(afr[ks][2], zsT[(k0 + tig + 4) * TP + t0]);
        CVT_TF32(afr[ks][3], zsT[(k0 + tig + 4) * TP + t1]);
    }
    float At0 = As[t0], At1 = As[t1];

    // ---- pass 1: approx min + candidate-tile mask ----
    float run0 = 3.4e38f, run1 = 3.4e38f;
    ull mask = 0ull;
    for (int n = 0; n < 64; n++) {
        int n0 = 8 * n;
        float c0 = 0.f, c1 = 0.f, c2 = 0.f, c3 = 0.f;
        #pragma unroll
        for (int ks = 0; ks < 8; ks++) {
            int k0 = 8 * ks;
            unsigned b0, b1;
            CVT_TF32(b0, eTs[(k0 + tig) * EP + n0 + g]);
            CVT_TF32(b1, eTs[(k0 + tig + 4) * EP + n0 + g]);
            MMA_TF32(c0, c1, c2, c3,
                     afr[ks][0], afr[ks][1], afr[ks][2], afr[ks][3], b0, b1);
        }
        int kA = n0 + 2 * tig;
        float bA = Bs[kA], bB = Bs[kA + 1];
        float dA0 = At0 + bA - c0, dB0 = At0 + bB - c1;
        float dA1 = At1 + bA - c2, dB1 = At1 + bB - c3;
        float tm0 = fminf(dA0, dB0), tm1 = fminf(dA1, dB1);
        run0 = fminf(run0, tm0);
        run1 = fminf(run1, tm1);
        if (tm0 <= run0 + EPSF || tm1 <= run1 + EPSF) mask |= (1ull << n);
    }
    // per-token approx min across the quad (lanes sharing g)
    run0 = fminf(run0, __shfl_xor_sync(0xffffffffu, run0, 1));
    run0 = fminf(run0, __shfl_xor_sync(0xffffffffu, run0, 2));
    run1 = fminf(run1, __shfl_xor_sync(0xffffffffu, run1, 1));
    run1 = fminf(run1, __shfl_xor_sync(0xffffffffu, run1, 2));
    float th0 = run0 + EPSF, th1 = run1 + EPSF;
    // union of tile masks across the warp
    #pragma unroll
    for (int off = 16; off >= 1; off >>= 1)
        mask |= __shfl_xor_sync(0xffffffffu, mask, off);

    // ---- pass 2: flagged tiles, exact recheck of candidates ----
    float best0 = 3.4e38f, best1 = 3.4e38f;
    int bi0 = 0, bi1 = 0;
    for (int n = 0; n < 64; n++) {
        if (!((mask >> n) & 1ull)) continue;
        int n0 = 8 * n;
        float c0 = 0.f, c1 = 0.f, c2 = 0.f, c3 = 0.f;
        #pragma unroll
        for (int ks = 0; ks < 8; ks++) {
            int k0 = 8 * ks;
            unsigned b0, b1;
            CVT_TF32(b0, eTs[(k0 + tig) * EP + n0 + g]);
            CVT_TF32(b1, eTs[(k0 + tig + 4) * EP + n0 + g]);
            MMA_TF32(c0, c1, c2, c3,
                     afr[ks][0], afr[ks][1], afr[ks][2], afr[ks][3], b0, b1);
        }
        int kA = n0 + 2 * tig;
        float bA = Bs[kA], bB = Bs[kA + 1];
        float dap[4] = {At0 + bA - c0, At0 + bB - c1,
                        At1 + bA - c2, At1 + bB - c3};
        // ascending-k candidate checks (c0 before c1 => first occurrence)
        #pragma unroll
        for (int q = 0; q < 4; q++) {
            int tok = (q < 2) ? t0 : t1;
            float th = (q < 2) ? th0 : th1;
            int k = kA + (q & 1);
            if (dap[q] <= th) {
                float m = 0.f;                    // bit-exact chain: fl(2z_d)*e_d
                #pragma unroll 8
                for (int d = 0; d < DIM; d++)
                    m = fmaf(zsT[d * TP + tok], eTs[d * EP + k], m);
                float Av = (q < 2) ? At0 : At1;
                float de = __fsub_rn(__fadd_rn(Av, (q & 1) ? bB : bA), m);
                if (q < 2) { if (de < best0) { best0 = de; bi0 = k; } }
                else       { if (de < best1) { best1 = de; bi1 = k; } }
            }
        }
    }

    // lex (dist, index) merge across the quad
    #pragma unroll
    for (int off = 2; off >= 1; off >>= 1) {
        float od = __shfl_xor_sync(0xffffffffu, best0, off);
        int oi = __shfl_xor_sync(0xffffffffu, bi0, off);
        if (od < best0 || (od == best0 && oi < bi0)) { best0 = od; bi0 = oi; }
        od = __shfl_xor_sync(0xffffffffu, best1, off);
        oi = __shfl_xor_sync(0xffffffffu, bi1, off);
        if (od < best1 || (od == best1 && oi < bi1)) { best1 = od; bi1 = oi; }
    }

    float lsum = 0.f;
    if (tig == 0) {
        g_idx[base + t0] = bi0;
        g_idx[base + t1] = bi1;
        atomicAdd(&g_counts[bi0], 1u);
        atomicAdd(&g_counts[bi1], 1u);
        lsum = best0 + best1;
    }
    // deterministic warp sum (tig!=0 lanes contribute 0)
    #pragma unroll
    for (int off = 16; off >= 1; off >>= 1)
        lsum += __shfl_xor_sync(0xffffffffu, lsum, off);
    if (lane == 0) lred[w] = lsum;
    __syncthreads();
    if (tid == 0) {
        float acc = 0.f;
        #pragma unroll
        for (int t = 0; t < 16; t++) acc += lred[t];
        g_loss_part[blockIdx.x] = acc;
    }
}

// ---------------- gather: out[n][i] = table[idx[n]][i] ---------------------
__global__ void k_gather(float* __restrict__ out) {
    __shared__ int sidx[32];
    int tid = threadIdx.x;
    size_t base = (size_t)blockIdx.x * 32;
    if (tid < 32) sidx[tid] = g_idx[base + tid];
    __syncthreads();
    int rr = tid >> 6, q = tid & 63;
    #pragma unroll
    for (int j = 0; j < 8; j++) {
        int t = j * 4 + rr;
        float4 v = *(const float4*)(g_table + (size_t)sidx[t] * IN_DIM + 4 * q);
        float* o = out + (base + t) * IN_DIM + 4 * q;
        o[0] = v.x; o[1] = v.y; o[2] = v.z; o[3] = v.w;
    }
}

// ---------------- final: loss + perplexity ---------------------------------
__global__ void k_final(float* __restrict__ out, int out_size) {
    __shared__ float red[512];
    int tid = threadIdx.x;

    unsigned int cnt = g_counts[tid];
    float p = (float)cnt * (1.0f / (float)N_TOK);
    red[tid] = p * logf(p + 1e-10f);
    __syncthreads();
    for (int st = 256; st > 0; st >>= 1) {
        if (tid < st) red[tid] += red[tid + st];
        __syncthreads();
    }
    float ent = -red[0];
    __syncthreads();

    red[tid] = (tid < 256) ? g_loss_part[tid] : 0.f;
    __syncthreads();
    for (int st = 256; st > 0; st >>= 1) {
        if (tid < st) red[tid] += red[tid + st];
        __syncthreads();
    }
    if (tid == 0) {
        out[0] = 1.25f * red[0] / (float)((size_t)N_TOK * DIM);
        out[out_size - 1] = expf(ent);
    }
}

// ---------------- launch ----------------
extern "C" void kernel_launch(void* const* d_in, const int* in_sizes, int n_in,
                              void* d_out, int out_size) {
    const float* x = nullptr;
    const float* enc_w = nullptr;
    const float* dec_w = nullptr;
    const float* cb = nullptr;
    for (int i = 0; i < n_in; i++) {
        const float* p = (const float*)d_in[i];
        int sz = in_sizes[i];
        if (sz == N_TOK * IN_DIM) x = p;
        else if (sz == KCODE * DIM) cb = p;
        else if (sz == IN_DIM * DIM) { if (!enc_w) enc_w = p; else dec_w = p; }
    }

    const int SM_ENC = (IN_DIM * DIM + 128 * XPC) * 4;                    // 100352
    const int SM_VQ  = (DIM * EP + DIM * TP + KCODE + 256 + 16) * 4;      // ~201.9KB
    cudaFuncSetAttribute(k_enc, cudaFuncAttributeMaxDynamicSharedMemorySize, SM_ENC);
    cudaFuncSetAttribute(k_vq,  cudaFuncAttributeMaxDynamicSharedMemorySize, SM_VQ);

    float* out = (float*)d_out;

    k_setup<<<65, 256>>>(cb);
    k_table<<<512, 256>>>(cb, dec_w);
    k_enc<<<N_TOK / 128, 256, SM_ENC>>>(x, enc_w);
    k_vq<<<N_TOK / 256, 512, SM_VQ>>>();
    k_gather<<<N_TOK / 32, 256>>>(out + 1);
    k_final<<<1, 512>>>(out, out_size);
}